// round 12
// baseline (speedup 1.0000x reference)
#include <cuda_runtime.h>
#include <cuda_fp16.h>
#include <cstdint>

#define TOKENS 8192
#define HIDDEN 4096
#define INTER  11008

// ---------------- scratch (device globals; no allocation allowed) ----------------
__device__ __half g_Xh[(size_t)TOKENS * HIDDEN];   //  64 MB
__device__ __half g_Wg[(size_t)INTER  * HIDDEN];   //  90 MB
__device__ __half g_Wu[(size_t)INTER  * HIDDEN];   //  90 MB
__device__ __half g_Wd[(size_t)HIDDEN * INTER];    //  90 MB
__device__ __half g_H [(size_t)TOKENS * INTER];    // 180 MB

// ---------------- base-target (sm_80-level) primitives only ----------------
__device__ __forceinline__ uint32_t smem_to_u32(const void* smem_ptr) {
    uint32_t addr;
    asm("{ .reg .u64 tmp; cvta.to.shared.u64 tmp, %1; cvt.u32.u64 %0, tmp; }"
        : "=r"(addr) : "l"(smem_ptr));
    return addr;
}

// SW128-style swizzle: XOR bits [6:4] with bits [9:7] (8 rows x 128B atom)
__device__ __forceinline__ uint32_t swz(uint32_t off) {
    return off ^ ((off >> 3) & 0x70);
}

#define CP_ASYNC16(dst, src) \
    asm volatile("cp.async.cg.shared.global [%0], [%1], 16;" \
        :: "r"(dst), "l"(src) : "memory")
#define CP_COMMIT() asm volatile("cp.async.commit_group;" ::: "memory")
#define CP_WAIT2()  asm volatile("cp.async.wait_group 2;" ::: "memory")

#define LDSM_X4(r, addr) \
    asm volatile("ldmatrix.sync.aligned.m8n8.x4.shared.b16 {%0,%1,%2,%3}, [%4];" \
        : "=r"((r)[0]), "=r"((r)[1]), "=r"((r)[2]), "=r"((r)[3]) : "r"(addr))

#define MMA_F16F32(c, a, b0, b1) \
    asm volatile("mma.sync.aligned.m16n8k16.row.col.f32.f16.f16.f32 " \
        "{%0,%1,%2,%3}, {%4,%5,%6,%7}, {%8,%9}, {%0,%1,%2,%3};" \
        : "+f"((c)[0]), "+f"((c)[1]), "+f"((c)[2]), "+f"((c)[3]) \
        : "r"((a)[0]), "r"((a)[1]), "r"((a)[2]), "r"((a)[3]), "r"(b0), "r"(b1))

// ---------------- geometry ----------------
static constexpr int BK          = 64;               // halfs; 128 B per row
static constexpr int A_BYTES     = 128 * 128;        // 16 KB
static constexpr int B_BYTES     = 256 * 128;        // 32 KB
static constexpr int STAGE_BYTES = A_BYTES + B_BYTES;           // 48 KB
static constexpr int SMEM_TOTAL  = 4 * STAGE_BYTES + 1024;      // 197632

// ---------------- fused convert: all 4 tensors in ONE launch (DRAM-bound) -----------
static constexpr size_t NX = (size_t)TOKENS * HIDDEN;   // 33.55M
static constexpr size_t NW = (size_t)INTER  * HIDDEN;   // 45.09M
static constexpr size_t CX = NX / 8, CW = NW / 8;       // 16B chunks
static constexpr size_t CHUNKS_TOTAL = CX + 3 * CW;     // 21,102,592 = 82432 * 256

__global__ void __launch_bounds__(256) cvt_all_kernel(
    const float* __restrict__ x,  const float* __restrict__ wg,
    const float* __restrict__ wu, const float* __restrict__ wd)
{
    size_t cid = (size_t)blockIdx.x * blockDim.x + threadIdx.x;
    const float* in;
    __half* out;
    if (cid < CX)               { in = x;  out = g_Xh; }
    else if (cid < CX + CW)     { in = wg; out = g_Wg; cid -= CX; }
    else if (cid < CX + 2 * CW) { in = wu; out = g_Wu; cid -= CX + CW; }
    else                        { in = wd; out = g_Wd; cid -= CX + 2 * CW; }
    size_t i = cid * 8;
    float4 a = *reinterpret_cast<const float4*>(in + i);
    float4 b = *reinterpret_cast<const float4*>(in + i + 4);
    __half2 h[4];
    h[0] = __floats2half2_rn(a.x, a.y);
    h[1] = __floats2half2_rn(a.z, a.w);
    h[2] = __floats2half2_rn(b.x, b.y);
    h[3] = __floats2half2_rn(b.z, b.w);
    *reinterpret_cast<uint4*>(out + i) = *reinterpret_cast<uint4*>(h);
}

// ==================================================================================
// GEMM1: H = SiLU(X @ Wg^T) * (X @ Wu^T).  CTA: 128 M x 128 H-cols, K=4096.
// 512 threads = 16 warps = 4(M) x 4(N); warp tile 32 M-rows x 32 H-cols (gate+up).
// B tile rows 0-127 = Wg band, rows 128-255 = Wu band.   (R7 mainloop + XOR-folded swz)
// Proof of fold: LDSM base offsets have bits[5:6]=0; ks*32 occupies bits[5:6];
// swizzle mask depends only on bits[7:9]  =>  swz(off + ks*32) == swz(off) ^ (ks*32).
// ==================================================================================
__global__ void __launch_bounds__(512, 1) gemm1_kernel() {
    extern __shared__ char smem[];
    uint32_t sb = (smem_to_u32(smem) + 1023) & ~1023u;
    int tid = threadIdx.x, lane = tid & 31, w = tid >> 5;
    int mw = w >> 2, nw = w & 3;
    int mtile = blockIdx.x, ntile = blockIdx.y;

    // ---- loader: 6 chunks/thread, src advances by BK halfs per kt ----
    const __half* src[6];
    uint32_t doff[6];
    {
        const __half* Ag = g_Xh + (size_t)mtile * 128 * HIDDEN;
        const __half* Gg = g_Wg + (size_t)ntile * 128 * HIDDEN;
        const __half* Ug = g_Wu + (size_t)ntile * 128 * HIDDEN;
        #pragma unroll
        for (int it = 0; it < 6; it++) {
            int idx = tid + it * 512;
            if (idx < 1024) {
                int r = idx >> 3, ck = idx & 7;
                doff[it] = swz(r * 128 + ck * 16);
                src[it]  = Ag + (size_t)r * HIDDEN + ck * 8;
            } else {
                int j = idx - 1024;
                int r = j >> 3, ck = j & 7;
                doff[it] = A_BYTES + swz(r * 128 + ck * 16);
                src[it]  = (r < 128) ? Gg + (size_t)r * HIDDEN + ck * 8
                                     : Ug + (size_t)(r - 128) * HIDDEN + ck * 8;
            }
        }
    }
    auto load_stage = [&](int s) {
        uint32_t st = sb + s * STAGE_BYTES;
        #pragma unroll
        for (int it = 0; it < 6; it++) {
            CP_ASYNC16(st + doff[it], src[it]);
            src[it] += BK;
        }
    };

    // ---- pre-swizzled ldmatrix per-lane base addresses ----
    uint32_t aoffS[2], bgS[2], buS[2];
    #pragma unroll
    for (int mi = 0; mi < 2; mi++)
        aoffS[mi] = swz((mw * 32 + mi * 16 + (lane & 15)) * 128 + ((lane >> 4) & 1) * 16);
    {
        uint32_t brow = (lane & 7) + ((lane >> 4) & 1) * 8;
        uint32_t bsel = ((lane >> 3) & 1) * 16;
        #pragma unroll
        for (int p = 0; p < 2; p++) {
            uint32_t bo = (nw * 32 + p * 16 + brow) * 128 + bsel;
            bgS[p] = A_BYTES + swz(bo);
            buS[p] = A_BYTES + swz(bo + 128 * 128);
        }
    }

    float cg[2][4][4] = {};
    float cu[2][4][4] = {};

    const int KT = HIDDEN / BK;   // 64
    load_stage(0); CP_COMMIT();
    load_stage(1); CP_COMMIT();
    load_stage(2); CP_COMMIT();

    for (int kt = 0; kt < KT; kt++) {
        CP_WAIT2();
        __syncthreads();
        if (kt + 3 < KT) load_stage((kt + 3) & 3);
        CP_COMMIT();

        uint32_t Sb = sb + (kt & 3) * STAGE_BYTES;
        #pragma unroll
        for (int ks = 0; ks < 4; ks++) {
            const uint32_t kx = ks * 32;
            uint32_t a[2][4], bg[2][4], bu[2][4];
            #pragma unroll
            for (int mi = 0; mi < 2; mi++) LDSM_X4(a[mi],  Sb + (aoffS[mi] ^ kx));
            #pragma unroll
            for (int p = 0; p < 2; p++)  LDSM_X4(bg[p], Sb + (bgS[p] ^ kx));
            #pragma unroll
            for (int p = 0; p < 2; p++)  LDSM_X4(bu[p], Sb + (buS[p] ^ kx));
            #pragma unroll
            for (int mi = 0; mi < 2; mi++)
                #pragma unroll
                for (int p = 0; p < 2; p++) {
                    MMA_F16F32(cg[mi][2 * p],     a[mi], bg[p][0], bg[p][1]);
                    MMA_F16F32(cg[mi][2 * p + 1], a[mi], bg[p][2], bg[p][3]);
                    MMA_F16F32(cu[mi][2 * p],     a[mi], bu[p][0], bu[p][1]);
                    MMA_F16F32(cu[mi][2 * p + 1], a[mi], bu[p][2], bu[p][3]);
                }
        }
    }

    // epilogue: SiLU(gate)*up -> fp16 H
    #pragma unroll
    for (int mi = 0; mi < 2; mi++) {
        int r0 = mtile * 128 + mw * 32 + mi * 16 + (lane >> 2);
        #pragma unroll
        for (int ni = 0; ni < 4; ni++) {
            int col = ntile * 128 + nw * 32 + ni * 8 + (lane & 3) * 2;
            float g0 = cg[mi][ni][0], g1 = cg[mi][ni][1];
            float g2 = cg[mi][ni][2], g3 = cg[mi][ni][3];
            float h0 = g0 / (1.0f + __expf(-g0)) * cu[mi][ni][0];
            float h1 = g1 / (1.0f + __expf(-g1)) * cu[mi][ni][1];
            float h2 = g2 / (1.0f + __expf(-g2)) * cu[mi][ni][2];
            float h3 = g3 / (1.0f + __expf(-g3)) * cu[mi][ni][3];
            *reinterpret_cast<__half2*>(g_H + (size_t)r0 * INTER + col)       = __floats2half2_rn(h0, h1);
            *reinterpret_cast<__half2*>(g_H + (size_t)(r0 + 8) * INTER + col) = __floats2half2_rn(h2, h3);
        }
    }
}

// ==================================================================================
// GEMM2: Out = H @ Wd^T.  BM=128, BN=256, K=11008.
// 512 threads = 16 warps = 4(M) x 4(N); warp tile 32 x 64.  (R7 mainloop + XOR-folded swz)
// ==================================================================================
__global__ void __launch_bounds__(512, 1) gemm2_kernel(float* __restrict__ out) {
    extern __shared__ char smem[];
    uint32_t sb = (smem_to_u32(smem) + 1023) & ~1023u;
    int tid = threadIdx.x, lane = tid & 31, w = tid >> 5;
    int mw = w >> 2, nw = w & 3;
    int ntile = blockIdx.x, mtile = blockIdx.y;     // n-fast: Wd band L2-resident

    const __half* srcp[6];
    uint32_t doff[6];
    {
        const __half* Hg = g_H  + (size_t)mtile * 128 * INTER;
        const __half* Dg = g_Wd + (size_t)ntile * 256 * INTER;
        #pragma unroll
        for (int it = 0; it < 6; it++) {
            int idx = tid + it * 512;
            if (idx < 1024) {
                int r = idx >> 3, ck = idx & 7;
                doff[it] = swz(r * 128 + ck * 16);
                srcp[it] = Hg + (size_t)r * INTER + ck * 8;
            } else {
                int j = idx - 1024;
                int r = j >> 3, ck = j & 7;
                doff[it] = A_BYTES + swz(r * 128 + ck * 16);
                srcp[it] = Dg + (size_t)r * INTER + ck * 8;
            }
        }
    }
    auto load_stage = [&](int s) {
        uint32_t st = sb + s * STAGE_BYTES;
        #pragma unroll
        for (int it = 0; it < 6; it++) {
            CP_ASYNC16(st + doff[it], srcp[it]);
            srcp[it] += BK;
        }
    };

    uint32_t aoffS[2], bS[4];
    #pragma unroll
    for (int mi = 0; mi < 2; mi++)
        aoffS[mi] = swz((mw * 32 + mi * 16 + (lane & 15)) * 128 + ((lane >> 4) & 1) * 16);
    {
        uint32_t brow = (lane & 7) + ((lane >> 4) & 1) * 8;
        uint32_t bsel = ((lane >> 3) & 1) * 16;
        #pragma unroll
        for (int p = 0; p < 4; p++)
            bS[p] = A_BYTES + swz((nw * 64 + p * 16 + brow) * 128 + bsel);
    }

    float c[2][8][4] = {};

    const int KT = INTER / BK;    // 172
    load_stage(0); CP_COMMIT();
    load_stage(1); CP_COMMIT();
    load_stage(2); CP_COMMIT();

    for (int kt = 0; kt < KT; kt++) {
        CP_WAIT2();
        __syncthreads();
        if (kt + 3 < KT) load_stage((kt + 3) & 3);
        CP_COMMIT();

        uint32_t Sb = sb + (kt & 3) * STAGE_BYTES;
        #pragma unroll
        for (int ks = 0; ks < 4; ks++) {
            const uint32_t kx = ks * 32;
            uint32_t a[2][4], b[4][4];
            #pragma unroll
            for (int mi = 0; mi < 2; mi++) LDSM_X4(a[mi], Sb + (aoffS[mi] ^ kx));
            #pragma unroll
            for (int p = 0; p < 4; p++)  LDSM_X4(b[p],  Sb + (bS[p] ^ kx));
            #pragma unroll
            for (int mi = 0; mi < 2; mi++)
                #pragma unroll
                for (int p = 0; p < 4; p++) {
                    MMA_F16F32(c[mi][2 * p],     a[mi], b[p][0], b[p][1]);
                    MMA_F16F32(c[mi][2 * p + 1], a[mi], b[p][2], b[p][3]);
                }
        }
    }

    #pragma unroll
    for (int mi = 0; mi < 2; mi++) {
        int r0 = mtile * 128 + mw * 32 + mi * 16 + (lane >> 2);
        #pragma unroll
        for (int ni = 0; ni < 8; ni++) {
            int col = ntile * 256 + nw * 64 + ni * 8 + (lane & 3) * 2;
            *reinterpret_cast<float2*>(out + (size_t)r0 * HIDDEN + col)       = make_float2(c[mi][ni][0], c[mi][ni][1]);
            *reinterpret_cast<float2*>(out + (size_t)(r0 + 8) * HIDDEN + col) = make_float2(c[mi][ni][2], c[mi][ni][3]);
        }
    }
}

// ---------------- host ----------------
extern "C" void kernel_launch(void* const* d_in, const int* in_sizes, int n_in,
                              void* d_out, int out_size)
{
    if (n_in < 4) return;
    const float* x  = (const float*)d_in[0];
    const float* wg = (const float*)d_in[1];
    const float* wu = (const float*)d_in[2];
    const float* wd = (const float*)d_in[3];

    // one fused convert launch (all 4 tensors)
    cvt_all_kernel<<<(unsigned)(CHUNKS_TOTAL / 256), 256>>>(x, wg, wu, wd);

    cudaFuncSetAttribute(gemm1_kernel, cudaFuncAttributeMaxDynamicSharedMemorySize, SMEM_TOTAL);
    cudaFuncSetAttribute(gemm2_kernel, cudaFuncAttributeMaxDynamicSharedMemorySize, SMEM_TOTAL);

    gemm1_kernel<<<dim3(TOKENS / 128, INTER / 128), 512, SMEM_TOTAL>>>();
    gemm2_kernel<<<dim3(HIDDEN / 256, TOKENS / 128), 512, SMEM_TOTAL>>>((float*)d_out);
}

// round 15
// speedup vs baseline: 1.0646x; 1.0646x over previous
#include <cuda_runtime.h>
#include <cuda_fp16.h>
#include <cstdint>

#define TOKENS 8192
#define HIDDEN 4096
#define INTER  11008

// ---------------- scratch (device globals; no allocation allowed) ----------------
__device__ __half g_Xh[(size_t)TOKENS * HIDDEN];   //  64 MB
__device__ __half g_Wg[(size_t)INTER  * HIDDEN];   //  90 MB
__device__ __half g_Wu[(size_t)INTER  * HIDDEN];   //  90 MB
__device__ __half g_Wd[(size_t)HIDDEN * INTER];    //  90 MB
__device__ __half g_H [(size_t)TOKENS * INTER];    // 180 MB

// ---------------- base-target (sm_80-level) primitives only ----------------
__device__ __forceinline__ uint32_t smem_to_u32(const void* smem_ptr) {
    uint32_t addr;
    asm("{ .reg .u64 tmp; cvta.to.shared.u64 tmp, %1; cvt.u32.u64 %0, tmp; }"
        : "=r"(addr) : "l"(smem_ptr));
    return addr;
}

// SW128-style swizzle: XOR bits [6:4] with bits [9:7] (8 rows x 128B atom)
__device__ __forceinline__ uint32_t swz(uint32_t off) {
    return off ^ ((off >> 3) & 0x70);
}

#define CP_ASYNC16(dst, src) \
    asm volatile("cp.async.cg.shared.global [%0], [%1], 16;" \
        :: "r"(dst), "l"(src) : "memory")
#define CP_COMMIT() asm volatile("cp.async.commit_group;" ::: "memory")
#define CP_WAIT2()  asm volatile("cp.async.wait_group 2;" ::: "memory")

#define LDSM_X4(r, addr) \
    asm volatile("ldmatrix.sync.aligned.m8n8.x4.shared.b16 {%0,%1,%2,%3}, [%4];" \
        : "=r"((r)[0]), "=r"((r)[1]), "=r"((r)[2]), "=r"((r)[3]) : "r"(addr))

#define MMA_F16F32(c, a, b0, b1) \
    asm volatile("mma.sync.aligned.m16n8k16.row.col.f32.f16.f16.f32 " \
        "{%0,%1,%2,%3}, {%4,%5,%6,%7}, {%8,%9}, {%0,%1,%2,%3};" \
        : "+f"((c)[0]), "+f"((c)[1]), "+f"((c)[2]), "+f"((c)[3]) \
        : "r"((a)[0]), "r"((a)[1]), "r"((a)[2]), "r"((a)[3]), "r"(b0), "r"(b1))

// ---------------- geometry ----------------
static constexpr int BK          = 64;               // halfs; 128 B per row
static constexpr int A_BYTES     = 128 * 128;        // 16 KB
static constexpr int B_BYTES     = 256 * 128;        // 32 KB
static constexpr int STAGE_BYTES = A_BYTES + B_BYTES;           // 48 KB
static constexpr int SMEM_TOTAL  = 4 * STAGE_BYTES + 1024;      // 197632

// ---------------- fused convert: all 4 tensors in ONE launch (DRAM-bound) -----------
static constexpr size_t NX = (size_t)TOKENS * HIDDEN;   // 33.55M
static constexpr size_t NW = (size_t)INTER  * HIDDEN;   // 45.09M
static constexpr size_t CX = NX / 8, CW = NW / 8;       // 16B chunks
static constexpr size_t CHUNKS_TOTAL = CX + 3 * CW;     // 21,102,592 = 82432 * 256

__global__ void __launch_bounds__(256) cvt_all_kernel(
    const float* __restrict__ x,  const float* __restrict__ wg,
    const float* __restrict__ wu, const float* __restrict__ wd)
{
    size_t cid = (size_t)blockIdx.x * blockDim.x + threadIdx.x;
    const float* in;
    __half* out;
    if (cid < CX)               { in = x;  out = g_Xh; }
    else if (cid < CX + CW)     { in = wg; out = g_Wg; cid -= CX; }
    else if (cid < CX + 2 * CW) { in = wu; out = g_Wu; cid -= CX + CW; }
    else                        { in = wd; out = g_Wd; cid -= CX + 2 * CW; }
    size_t i = cid * 8;
    float4 a = *reinterpret_cast<const float4*>(in + i);
    float4 b = *reinterpret_cast<const float4*>(in + i + 4);
    __half2 h[4];
    h[0] = __floats2half2_rn(a.x, a.y);
    h[1] = __floats2half2_rn(a.z, a.w);
    h[2] = __floats2half2_rn(b.x, b.y);
    h[3] = __floats2half2_rn(b.z, b.w);
    *reinterpret_cast<uint4*>(out + i) = *reinterpret_cast<uint4*>(h);
}

// ==================================================================================
// GEMM1: H = SiLU(X @ Wg^T) * (X @ Wu^T).  CTA: 128 M x 128 H-cols, K=4096.
// 512 threads = 16 warps = 4(M) x 4(N); warp tile 32 M-rows x 32 H-cols (gate+up).
// B tile rows 0-127 = Wg band, rows 128-255 = Wu band.
// R11 golden mainloop body; kt-loop split into steady-state (unconditional
// prefetch) + 3-iteration drain to remove the per-kt branch.
// ==================================================================================

// golden per-kt body, GEMM1 (identical instruction sequence to R11)
#define G1_BODY(Ab, Bb) \
    { \
        uint32_t Ab_ = (Ab), Bb_ = (Bb); \
        _Pragma("unroll") \
        for (int ks = 0; ks < 4; ks++) { \
            uint32_t a[2][4], bg[2][4], bu[2][4]; \
            _Pragma("unroll") \
            for (int mi = 0; mi < 2; mi++) LDSM_X4(a[mi],  Ab_ + swz(aoff[mi]  + ks * 32)); \
            _Pragma("unroll") \
            for (int p = 0; p < 2; p++)  LDSM_X4(bg[p], Bb_ + swz(bgoff[p] + ks * 32)); \
            _Pragma("unroll") \
            for (int p = 0; p < 2; p++)  LDSM_X4(bu[p], Bb_ + swz(buoff[p] + ks * 32)); \
            _Pragma("unroll") \
            for (int mi = 0; mi < 2; mi++) \
                _Pragma("unroll") \
                for (int p = 0; p < 2; p++) { \
                    MMA_F16F32(cg[mi][2 * p],     a[mi], bg[p][0], bg[p][1]); \
                    MMA_F16F32(cg[mi][2 * p + 1], a[mi], bg[p][2], bg[p][3]); \
                    MMA_F16F32(cu[mi][2 * p],     a[mi], bu[p][0], bu[p][1]); \
                    MMA_F16F32(cu[mi][2 * p + 1], a[mi], bu[p][2], bu[p][3]); \
                } \
        } \
    }

__global__ void __launch_bounds__(512, 1) gemm1_kernel() {
    extern __shared__ char smem[];
    uint32_t sb = (smem_to_u32(smem) + 1023) & ~1023u;
    int tid = threadIdx.x, lane = tid & 31, w = tid >> 5;
    int mw = w >> 2, nw = w & 3;
    int mtile = blockIdx.x, ntile = blockIdx.y;

    // ---- loader: 6 chunks/thread, src advances by BK halfs per kt ----
    const __half* src[6];
    uint32_t doff[6];
    {
        const __half* Ag = g_Xh + (size_t)mtile * 128 * HIDDEN;
        const __half* Gg = g_Wg + (size_t)ntile * 128 * HIDDEN;
        const __half* Ug = g_Wu + (size_t)ntile * 128 * HIDDEN;
        #pragma unroll
        for (int it = 0; it < 6; it++) {
            int idx = tid + it * 512;
            if (idx < 1024) {
                int r = idx >> 3, ck = idx & 7;
                doff[it] = swz(r * 128 + ck * 16);
                src[it]  = Ag + (size_t)r * HIDDEN + ck * 8;
            } else {
                int j = idx - 1024;
                int r = j >> 3, ck = j & 7;
                doff[it] = A_BYTES + swz(r * 128 + ck * 16);
                src[it]  = (r < 128) ? Gg + (size_t)r * HIDDEN + ck * 8
                                     : Ug + (size_t)(r - 128) * HIDDEN + ck * 8;
            }
        }
    }
    auto load_stage = [&](int s) {
        uint32_t st = sb + s * STAGE_BYTES;
        #pragma unroll
        for (int it = 0; it < 6; it++) {
            CP_ASYNC16(st + doff[it], src[it]);
            src[it] += BK;
        }
    };

    // ---- ldmatrix per-lane offsets ----
    uint32_t aoff[2], bgoff[2], buoff[2];
    #pragma unroll
    for (int mi = 0; mi < 2; mi++)
        aoff[mi] = (mw * 32 + mi * 16 + (lane & 15)) * 128 + ((lane >> 4) & 1) * 16;
    {
        uint32_t brow = (lane & 7) + ((lane >> 4) & 1) * 8;
        uint32_t bsel = ((lane >> 3) & 1) * 16;
        #pragma unroll
        for (int p = 0; p < 2; p++) {
            bgoff[p] = (nw * 32 + p * 16 + brow) * 128 + bsel;
            buoff[p] = bgoff[p] + 128 * 128;
        }
    }

    float cg[2][4][4] = {};
    float cu[2][4][4] = {};

    const int KT = HIDDEN / BK;   // 64
    load_stage(0); CP_COMMIT();
    load_stage(1); CP_COMMIT();
    load_stage(2); CP_COMMIT();

    // steady state: unconditional prefetch
    for (int kt = 0; kt < KT - 3; kt++) {
        CP_WAIT2();
        __syncthreads();
        load_stage((kt + 3) & 3);
        CP_COMMIT();
        uint32_t Ab = sb + (kt & 3) * STAGE_BYTES;
        G1_BODY(Ab, Ab + A_BYTES);
    }
    // drain: no prefetch
    for (int kt = KT - 3; kt < KT; kt++) {
        CP_WAIT2();
        __syncthreads();
        CP_COMMIT();
        uint32_t Ab = sb + (kt & 3) * STAGE_BYTES;
        G1_BODY(Ab, Ab + A_BYTES);
    }

    // epilogue: SiLU(gate)*up -> fp16 H
    #pragma unroll
    for (int mi = 0; mi < 2; mi++) {
        int r0 = mtile * 128 + mw * 32 + mi * 16 + (lane >> 2);
        #pragma unroll
        for (int ni = 0; ni < 4; ni++) {
            int col = ntile * 128 + nw * 32 + ni * 8 + (lane & 3) * 2;
            float g0 = cg[mi][ni][0], g1 = cg[mi][ni][1];
            float g2 = cg[mi][ni][2], g3 = cg[mi][ni][3];
            float h0 = g0 / (1.0f + __expf(-g0)) * cu[mi][ni][0];
            float h1 = g1 / (1.0f + __expf(-g1)) * cu[mi][ni][1];
            float h2 = g2 / (1.0f + __expf(-g2)) * cu[mi][ni][2];
            float h3 = g3 / (1.0f + __expf(-g3)) * cu[mi][ni][3];
            *reinterpret_cast<__half2*>(g_H + (size_t)r0 * INTER + col)       = __floats2half2_rn(h0, h1);
            *reinterpret_cast<__half2*>(g_H + (size_t)(r0 + 8) * INTER + col) = __floats2half2_rn(h2, h3);
        }
    }
}

// ==================================================================================
// GEMM2: Out = H @ Wd^T.  BM=128, BN=256, K=11008.
// 512 threads = 16 warps = 4(M) x 4(N); warp tile 32 x 64.  R11 golden body; split loop.
// ==================================================================================
#define G2_BODY(Ab, Bb) \
    { \
        uint32_t Ab_ = (Ab), Bb_ = (Bb); \
        _Pragma("unroll") \
        for (int ks = 0; ks < 4; ks++) { \
            uint32_t a[2][4], b[4][4]; \
            _Pragma("unroll") \
            for (int mi = 0; mi < 2; mi++) LDSM_X4(a[mi], Ab_ + swz(aoff[mi] + ks * 32)); \
            _Pragma("unroll") \
            for (int p = 0; p < 4; p++)  LDSM_X4(b[p],  Bb_ + swz(boff[p] + ks * 32)); \
            _Pragma("unroll") \
            for (int mi = 0; mi < 2; mi++) \
                _Pragma("unroll") \
                for (int p = 0; p < 4; p++) { \
                    MMA_F16F32(c[mi][2 * p],     a[mi], b[p][0], b[p][1]); \
                    MMA_F16F32(c[mi][2 * p + 1], a[mi], b[p][2], b[p][3]); \
                } \
        } \
    }

__global__ void __launch_bounds__(512, 1) gemm2_kernel(float* __restrict__ out) {
    extern __shared__ char smem[];
    uint32_t sb = (smem_to_u32(smem) + 1023) & ~1023u;
    int tid = threadIdx.x, lane = tid & 31, w = tid >> 5;
    int mw = w >> 2, nw = w & 3;
    int ntile = blockIdx.x, mtile = blockIdx.y;     // n-fast: Wd band L2-resident

    const __half* srcp[6];
    uint32_t doff[6];
    {
        const __half* Hg = g_H  + (size_t)mtile * 128 * INTER;
        const __half* Dg = g_Wd + (size_t)ntile * 256 * INTER;
        #pragma unroll
        for (int it = 0; it < 6; it++) {
            int idx = tid + it * 512;
            if (idx < 1024) {
                int r = idx >> 3, ck = idx & 7;
                doff[it] = swz(r * 128 + ck * 16);
                srcp[it] = Hg + (size_t)r * INTER + ck * 8;
            } else {
                int j = idx - 1024;
                int r = j >> 3, ck = j & 7;
                doff[it] = A_BYTES + swz(r * 128 + ck * 16);
                srcp[it] = Dg + (size_t)r * INTER + ck * 8;
            }
        }
    }
    auto load_stage = [&](int s) {
        uint32_t st = sb + s * STAGE_BYTES;
        #pragma unroll
        for (int it = 0; it < 6; it++) {
            CP_ASYNC16(st + doff[it], srcp[it]);
            srcp[it] += BK;
        }
    };

    uint32_t aoff[2], boff[4];
    #pragma unroll
    for (int mi = 0; mi < 2; mi++)
        aoff[mi] = (mw * 32 + mi * 16 + (lane & 15)) * 128 + ((lane >> 4) & 1) * 16;
    {
        uint32_t brow = (lane & 7) + ((lane >> 4) & 1) * 8;
        uint32_t bsel = ((lane >> 3) & 1) * 16;
        #pragma unroll
        for (int p = 0; p < 4; p++)
            boff[p] = (nw * 64 + p * 16 + brow) * 128 + bsel;
    }

    float c[2][8][4] = {};

    const int KT = INTER / BK;    // 172
    load_stage(0); CP_COMMIT();
    load_stage(1); CP_COMMIT();
    load_stage(2); CP_COMMIT();

    for (int kt = 0; kt < KT - 3; kt++) {
        CP_WAIT2();
        __syncthreads();
        load_stage((kt + 3) & 3);
        CP_COMMIT();
        uint32_t Ab = sb + (kt & 3) * STAGE_BYTES;
        G2_BODY(Ab, Ab + A_BYTES);
    }
    for (int kt = KT - 3; kt < KT; kt++) {
        CP_WAIT2();
        __syncthreads();
        CP_COMMIT();
        uint32_t Ab = sb + (kt & 3) * STAGE_BYTES;
        G2_BODY(Ab, Ab + A_BYTES);
    }

    #pragma unroll
    for (int mi = 0; mi < 2; mi++) {
        int r0 = mtile * 128 + mw * 32 + mi * 16 + (lane >> 2);
        #pragma unroll
        for (int ni = 0; ni < 8; ni++) {
            int col = ntile * 256 + nw * 64 + ni * 8 + (lane & 3) * 2;
            *reinterpret_cast<float2*>(out + (size_t)r0 * HIDDEN + col)       = make_float2(c[mi][ni][0], c[mi][ni][1]);
            *reinterpret_cast<float2*>(out + (size_t)(r0 + 8) * HIDDEN + col) = make_float2(c[mi][ni][2], c[mi][ni][3]);
        }
    }
}

// ---------------- host ----------------
extern "C" void kernel_launch(void* const* d_in, const int* in_sizes, int n_in,
                              void* d_out, int out_size)
{
    if (n_in < 4) return;
    const float* x  = (const float*)d_in[0];
    const float* wg = (const float*)d_in[1];
    const float* wu = (const float*)d_in[2];
    const float* wd = (const float*)d_in[3];

    // one fused convert launch (all 4 tensors)
    cvt_all_kernel<<<(unsigned)(CHUNKS_TOTAL / 256), 256>>>(x, wg, wu, wd);

    cudaFuncSetAttribute(gemm1_kernel, cudaFuncAttributeMaxDynamicSharedMemorySize, SMEM_TOTAL);
    cudaFuncSetAttribute(gemm2_kernel, cudaFuncAttributeMaxDynamicSharedMemorySize, SMEM_TOTAL);

    gemm1_kernel<<<dim3(TOKENS / 128, INTER / 128), 512, SMEM_TOTAL>>>();
    gemm2_kernel<<<dim3(HIDDEN / 256, TOKENS / 128), 512, SMEM_TOTAL>>>((float*)d_out);
}